// round 4
// baseline (speedup 1.0000x reference)
#include <cuda_runtime.h>

// Row size in elements: C*W*H = 512*7*7 (fixed per metadata).
#define ROW_ELEMS 25088
#define ROW_VEC4  (ROW_ELEMS / 4)   // 6272 float4 per row

#define PERSISTENT_BLOCKS 1184      // 148 SMs x 8 blocks/SM (256 thr, 31 regs)

// Persistent fused kernel: grid-stride over output rows (r = 3*p + j).
// Each iteration derives its source input row from r + obj_num (tiny scalar
// loop, amortized over a 100 KB copy), then does a plain vectorized float4
// row copy. No cache hints (R2: .cs dropped HBM BW 6023 -> 5445 GB/s).
// Persistent grid removes the 4 wave transitions of the 5760-block launch
// (~2360 cyc each per the B300 chip model).
__global__ void __launch_bounds__(256) gather_persist_kernel(
    const float4* __restrict__ in, float4* __restrict__ out,
    const int* __restrict__ obj_num, int n_images, int out_rows) {

    for (int r = blockIdx.x; r < out_rows; r += PERSISTENT_BLOCKS) {
        int p = r / 3;        // global pair index
        int j = r - 3 * p;    // 0 = o1 feat, 1 = o2 feat, 2 = union feat

        // Locate the image containing pair p (n_images <= 16; obj_num is
        // L1-resident after first touch).
        int pair_base = 0;    // pairs before this image
        int row_begin = 0;    // input rows before this image
        int n = 0;
        for (int i = 0; i < n_images; ++i) {
            n = obj_num[i];
            int np = n * (n - 1) / 2;
            if (p < pair_base + np) break;
            pair_base += np;
            row_begin += n * (n + 1) / 2;
        }
        int u = p - pair_base;   // pair index within image

        // Invert row-major triangular enumeration to (o1, o2).
        int o1 = 0, s = 0;
        while (s + (n - 1 - o1) <= u) {
            s += (n - 1 - o1);
            ++o1;
        }
        int o2 = o1 + 1 + (u - s);

        int src_row = (j == 0) ? (row_begin + o1)
                    : (j == 1) ? (row_begin + o2)
                               : (row_begin + n + u);

        const float4* __restrict__ src = in + (long long)src_row * ROW_VEC4;
        float4* __restrict__ dst = out + (long long)r * ROW_VEC4;

        #pragma unroll 8
        for (int i = threadIdx.x; i < ROW_VEC4; i += 256) {
            dst[i] = src[i];
        }
    }
}

extern "C" void kernel_launch(void* const* d_in, const int* in_sizes, int n_in,
                              void* d_out, int out_size) {
    const float* feats = (const float*)d_in[0];
    // d_in[1] is batch_size scalar; d_in[2] is obj_num array.
    const int* obj_num = (const int*)d_in[2];
    int n_images = in_sizes[2];

    int out_rows = out_size / ROW_ELEMS;      // = 3 * P

    int grid = out_rows < PERSISTENT_BLOCKS ? out_rows : PERSISTENT_BLOCKS;
    gather_persist_kernel<<<grid, 256>>>((const float4*)feats, (float4*)d_out,
                                         obj_num, n_images, out_rows);
}

// round 6
// speedup vs baseline: 1.2035x; 1.2035x over previous
#include <cuda_runtime.h>

// Row size in elements: C*W*H = 512*7*7 (fixed per metadata).
#define ROW_ELEMS 25088
#define ROW_VEC4  (ROW_ELEMS / 4)   // 6272 float4 per row
#define HALF_VEC4 (ROW_VEC4 / 2)    // 3136 float4 per half-row (50 KB)

// One block per output HALF-row. Finer work quanta than R3's full-row blocks
// -> tighter tail packing by the HW work-steal scheduler. Copy loop and cache
// policy identical to R3 (plain float4; .cs hints regressed in R2, persistent
// grid regressed in R4).
__global__ void __launch_bounds__(256) gather_half_kernel(
    const float4* __restrict__ in, float4* __restrict__ out,
    const int* __restrict__ obj_num, int n_images) {

    int br = blockIdx.x;
    int r  = br >> 1;          // output row index = 3*p + j
    int hv = (br & 1) * HALF_VEC4;  // half offset in vec4 units

    int p = r / 3;             // global pair index
    int j = r - 3 * p;         // 0 = o1 feat, 1 = o2 feat, 2 = union feat

    // Locate the image containing pair p (n_images <= 16; obj_num L1-resident
    // after first touch).
    int pair_base = 0;         // pairs before this image
    int row_begin = 0;         // input rows before this image
    int n = 0;
    for (int i = 0; i < n_images; ++i) {
        n = obj_num[i];
        int np = n * (n - 1) / 2;
        if (p < pair_base + np) break;
        pair_base += np;
        row_begin += n * (n + 1) / 2;
    }
    int u = p - pair_base;     // pair index within image

    // Invert row-major triangular enumeration to (o1, o2).
    int o1 = 0, s = 0;
    while (s + (n - 1 - o1) <= u) {
        s += (n - 1 - o1);
        ++o1;
    }
    int o2 = o1 + 1 + (u - s);

    int src_row = (j == 0) ? (row_begin + o1)
                : (j == 1) ? (row_begin + o2)
                           : (row_begin + n + u);

    const float4* __restrict__ src = in + (long long)src_row * ROW_VEC4 + hv;
    float4* __restrict__ dst = out + (long long)r * ROW_VEC4 + hv;

    #pragma unroll 8
    for (int i = threadIdx.x; i < HALF_VEC4; i += 256) {
        dst[i] = src[i];
    }
}

extern "C" void kernel_launch(void* const* d_in, const int* in_sizes, int n_in,
                              void* d_out, int out_size) {
    const float* feats = (const float*)d_in[0];
    // d_in[1] is batch_size scalar; d_in[2] is obj_num array.
    const int* obj_num = (const int*)d_in[2];
    int n_images = in_sizes[2];

    int out_rows = out_size / ROW_ELEMS;      // = 3 * P

    gather_half_kernel<<<out_rows * 2, 256>>>((const float4*)feats,
                                              (float4*)d_out,
                                              obj_num, n_images);
}